// round 17
// baseline (speedup 1.0000x reference)
#include <cuda_runtime.h>
#include <cstdint>

#define KTOT   4194304
#define CHUNK  64                      // outputs per chain
#define WARM   128                     // warmup window (tile alignment)
#define TS     32                      // steps per tile
#define NT     6                       // tiles per chain
#define WTILES 4                       // warmup tiles (tile 0 half-skipped: eff 112)
#define NCH    (KTOT / CHUNK)          // 65536 chains (1 per thread)
#define WPB    2                       // warps per block
#define TPB    (WPB * 32)
#define NBLK   (NCH / 32 / WPB)        // 1024 blocks (2048 warps)
#define PITCH  34                      // buffer row pitch in floats
#define BROWS  34                      // rows per parity buffer (32 + 2 shift)
#define SGP    34                      // sigma buffer pitch (full tile + pad)

__device__ __forceinline__ float frcp_ap(float x) {
    float r; asm("rcp.approx.ftz.f32 %0, %1;" : "=f"(r) : "f"(x)); return r;
}
__device__ __forceinline__ float fsqrt_ap(float x) {
    float r; asm("sqrt.approx.f32 %0, %1;" : "=f"(r) : "f"(x)); return r;
}
__device__ __forceinline__ void cp_async8(uint32_t dst, const float* src) {
    asm volatile("cp.async.ca.shared.global [%0], [%1], 8;" :: "r"(dst), "l"(src));
}
#define CP_COMMIT() asm volatile("cp.async.commit_group;" ::: "memory")
#define CP_WAIT1()  asm volatile("cp.async.wait_group 1;"  ::: "memory")
#define CP_WAIT0()  asm volatile("cp.async.wait_group 0;"  ::: "memory")

struct P { float nu, Amu, As, bmu, Bs, wmu, ws; };

// 28-cycle recurrence: carries (mu, s2, nus2 = nu*s2).
__device__ __forceinline__ void gas_step(
    const float y, float& mu, float& s2, float& nus2, const P& p)
{
    const float r_  = y - mu;
    const float d   = fmaf(r_, r_, nus2);        // critical: no rr detour
    const float q   = frcp_ap(d);
    const float rr  = r_ * r_;                   // off-path
    const float a1  = p.Amu * (s2 * r_);         // ready inside RCP shadow
    const float a2  = p.As  * (s2 * rr);
    const float mb  = fmaf(p.bmu, mu, p.wmu);
    const float sb  = fmaf(p.Bs,  s2, p.ws);
    mu   = fmaf(a1, q, mb);
    s2   = fmaf(a2, q, sb);
    nus2 = p.nu * s2;
}

// Stage rows 0..31 of a parity buffer. Row r holds y[base + 64r, +32).
template<bool GUARD>
__device__ __forceinline__ void stage_init(
    const int base, const int lane, const float* __restrict__ y, float* buf)
{
    const int r0  = lane >> 4;
    const int col = (lane & 15) * 2;
    uint32_t dst = (uint32_t)__cvta_generic_to_shared(buf + r0 * PITCH + col);
    const int g0 = base + r0 * 64 + col;
    #pragma unroll
    for (int k = 0; k < 16; ++k) {
        int g = g0 + k * 128;
        if (GUARD) g = max(g, 0);
        cp_async8(dst + (uint32_t)(k * (2 * PITCH * 4)), y + g);
    }
    CP_COMMIT();
}

// Stage one extension row (32 floats); all lanes commit.
__device__ __forceinline__ void stage_row(
    const int row, const int base, const int lane,
    const float* __restrict__ y, float* buf)
{
    if (lane < 16) {
        uint32_t dst = (uint32_t)__cvta_generic_to_shared(buf + row * PITCH + lane * 2);
        cp_async8(dst, y + base + 64 * row + lane * 2);
    }
    CP_COMMIT();
}

// Warmup half-tile (16 steps) from register preload.
template<bool GUARD>
__device__ __forceinline__ void warm_half(
    const int t, const int h, const int skip,
    float* rp, float& mu, float& s2, float& nus2, const P& p)
{
    float2 v[8];
    #pragma unroll
    for (int i = 0; i < 8; ++i)
        v[i] = *reinterpret_cast<const float2*>(rp + 16 * h + 2 * i);
    #pragma unroll
    for (int i = 0; i < 8; ++i) {
        if (GUARD) {
            if (t * TS + 16 * h + 2 * i     >= skip) gas_step(v[i].x, mu, s2, nus2, p);
            if (t * TS + 16 * h + 2 * i + 1 >= skip) gas_step(v[i].y, mu, s2, nus2, p);
        } else {
            gas_step(v[i].x, mu, s2, nus2, p);
            gas_step(v[i].y, mu, s2, nus2, p);
        }
    }
}

// Emit half-tile: 16 steps, mu in place (own dead row), sigma (sqrt inline)
// to sgr. If FL, interleave one flush iteration of the PREVIOUS half per
// step-pair: pure LDS->STG copies riding in the RCP shadow.
template<bool FL>
__device__ __forceinline__ void emit_half(
    const int h, const int wcb, const int lane,
    float* rp, float* sgr,
    const int tp, const int hp, const float* bpp,   // prev half: tile, half, mu buffer
    const float* sg, float* __restrict__ out,
    float& mu, float& s2, float& nus2, const P& p)
{
    float2 v[8];
    #pragma unroll
    for (int i = 0; i < 8; ++i)
        v[i] = *reinterpret_cast<const float2*>(rp + 16 * h + 2 * i);
    const int r0s = lane >> 3;
    const int cs  = (lane & 7) * 2;
    #pragma unroll
    for (int i = 0; i < 8; ++i) {
        gas_step(v[i].x, mu, s2, nus2, p);
        const float m0 = mu, v0 = s2;
        gas_step(v[i].y, mu, s2, nus2, p);
        *reinterpret_cast<float2*>(rp  + 16 * h + 2 * i) = make_float2(m0, mu);
        *reinterpret_cast<float2*>(sgr + 16 * h + 2 * i) =
            make_float2(fsqrt_ap(v0), fsqrt_ap(s2));
        if (FL) {
            const int row = 4 * i + r0s;
            const int obp = (tp - WTILES) * TS + 16 * hp;
            const int gi  = (wcb + row) * CHUNK + obp + cs;
            const float2 g = *reinterpret_cast<const float2*>(
                sg + row * SGP + 16 * hp + cs);
            const float2 m = *reinterpret_cast<const float2*>(
                bpp + (row + 2) * PITCH + 16 * hp + cs);
            *reinterpret_cast<float2*>(&out[KTOT + gi]) = g;
            *reinterpret_cast<float2*>(&out[gi])        = m;
        }
    }
}

// Standalone flush of the last half (tile 5, h=1).
__device__ __forceinline__ void flush_final(
    const int wcb, const int lane,
    const float* bpO, const float* sg, float* __restrict__ out)
{
    const int r0s = lane >> 3;
    const int cs  = (lane & 7) * 2;
    #pragma unroll
    for (int k = 0; k < 8; ++k) {
        const int row = 4 * k + r0s;
        const int gi  = (wcb + row) * CHUNK + 48 + cs;   // (5-4)*32 + 16
        const float2 g = *reinterpret_cast<const float2*>(sg + row * SGP + 16 + cs);
        const float2 m = *reinterpret_cast<const float2*>(
            bpO + (row + 2) * PITCH + 16 + cs);
        *reinterpret_cast<float2*>(&out[KTOT + gi]) = g;
        *reinterpret_cast<float2*>(&out[gi])        = m;
    }
}

template<bool GUARD>
__device__ __forceinline__ void run_warp(
    const int wcb, const int lane,
    const float* __restrict__ y, float* __restrict__ out,
    float* bufE, float* bufO, float* sg,
    float mu, float s2, float nus2, const P& p, const int skip)
{
    const int baseE = wcb * CHUNK - WARM;
    const int baseO = baseE + 32;

    stage_init<GUARD>(baseE, lane, y, bufE);     // group 0
    stage_init<GUARD>(baseO, lane, y, bufO);     // group 1

    // warmup tiles 0..3 (stage extension rows for tiles 2..5 along the way)
    #pragma unroll 1
    for (int t = 0; t < WTILES; ++t) {
        CP_WAIT1();
        __syncwarp();
        float* bp = (t & 1) ? bufO : bufE;
        float* rp = bp + (lane + (t >> 1)) * PITCH;
        stage_row(31 + ((t + 2) >> 1), (t & 1) ? baseO : baseE, lane, y, bp);
        if (GUARD) {
            if (t > 0) warm_half<true>(t, 0, skip, rp, mu, s2, nus2, p);
            warm_half<true>(t, 1, skip, rp, mu, s2, nus2, p);
        } else {
            if (t > 0) warm_half<false>(t, 0, skip, rp, mu, s2, nus2, p);
            warm_half<false>(t, 1, skip, rp, mu, s2, nus2, p);
        }
    }

    float* sgr = sg + lane * SGP;

    // tile 4 (bufE, row offset 2)
    CP_WAIT1();
    __syncwarp();
    float* rp4 = bufE + (lane + 2) * PITCH;
    emit_half<false>(0, wcb, lane, rp4, sgr, 0, 0, bufE, sg, out, mu, s2, nus2, p);
    __syncwarp();
    emit_half<true >(1, wcb, lane, rp4, sgr, 4, 0, bufE, sg, out, mu, s2, nus2, p);
    __syncwarp();

    // tile 5 (bufO, row offset 2)
    CP_WAIT0();
    __syncwarp();
    float* rp5 = bufO + (lane + 2) * PITCH;
    emit_half<true >(0, wcb, lane, rp5, sgr, 4, 1, bufE, sg, out, mu, s2, nus2, p);
    __syncwarp();
    emit_half<true >(1, wcb, lane, rp5, sgr, 5, 0, bufO, sg, out, mu, s2, nus2, p);
    __syncwarp();

    flush_final(wcb, lane, bufO, sg, out);
}

__global__ __launch_bounds__(TPB)
void argas_kernel(
    const float* __restrict__ y,
    const float* __restrict__ p_lastmu,  const float* __restrict__ p_lastsig,
    const float* __restrict__ p_amu,     const float* __restrict__ p_as,
    const float* __restrict__ p_bmu,     const float* __restrict__ p_bs,
    const float* __restrict__ p_wmu,     const float* __restrict__ p_ws,
    const float* __restrict__ p_nu,      const float* __restrict__ p_str,
    float* __restrict__ out)
{
    __shared__ float bufE[WPB][BROWS][PITCH];
    __shared__ float bufO[WPB][BROWS][PITCH];
    __shared__ float sg[WPB][32][SGP];

    const int warp  = threadIdx.x >> 5;
    const int lane  = threadIdx.x & 31;
    const int wcb   = (blockIdx.x * WPB + warp) * 32;
    const int chain = wcb + lane;

    P p;
    const float nu       = *p_nu;
    const float strength = *p_str;
    const float amu  = (*p_amu) * strength;
    const float as_  = (*p_as)  * strength;
    const float bmu  = *p_bmu;
    const float bs   = *p_bs;
    const float nup1 = nu + 1.0f;
    p.nu  = nu;
    p.Amu = bmu * amu * nup1;
    p.As  = bs  * as_ * nup1;
    p.bmu = bmu;
    p.Bs  = bs * (1.0f - as_);
    p.wmu = *p_wmu;
    p.ws  = *p_ws;

    const float mu0   = *p_lastmu;
    const float s20   = *p_lastsig;
    const float nus20 = nu * s20;

    const int skip = WARM - chain * CHUNK;   // >0 only for chains 0,1 (warp 0)

    if (wcb == 0)
        run_warp<true >(wcb, lane, y, out,
                        &bufE[warp][0][0], &bufO[warp][0][0], &sg[warp][0][0],
                        mu0, s20, nus20, p, skip);
    else
        run_warp<false>(wcb, lane, y, out,
                        &bufE[warp][0][0], &bufO[warp][0][0], &sg[warp][0][0],
                        mu0, s20, nus20, p, skip);
}

extern "C" void kernel_launch(void* const* d_in, const int* in_sizes, int n_in,
                              void* d_out, int out_size) {
    const float* y = (const float*)d_in[0];
    argas_kernel<<<NBLK, TPB>>>(
        y,
        (const float*)d_in[1],  (const float*)d_in[2],
        (const float*)d_in[3],  (const float*)d_in[4],
        (const float*)d_in[5],  (const float*)d_in[6],
        (const float*)d_in[7],  (const float*)d_in[8],
        (const float*)d_in[9],  (const float*)d_in[10],
        (float*)d_out);
}